// round 10
// baseline (speedup 1.0000x reference)
#include <cuda_runtime.h>
#include <math.h>

#define B_ 2
#define N_ 1024
#define M_ 1024
#define H_ 128
#define GRID_ 128
#define THREADS_ 512

// Device scratch (no allocations allowed)
__device__ __align__(16) float g_e[B_ * M_];   // exp(scale*ks[m])
__device__ __align__(16) float g_psum[GRID_];  // per-block partial sums (64/batch)
__device__ unsigned g_bar_count;               // zero-init; self-resetting
__device__ volatile unsigned g_bar_sense;      // alternates across launches

// ---------------------------------------------------------------------------
// One persistent kernel, grid = 128 blocks x 512 threads (<= 148 SMs, so all
// blocks are co-resident: device grid barrier is safe).
//
// Phase 1: block bid owns 16 key rows m = (bid&63)*16 + warp of batch bid>>6.
//   wcol[h] = sum_o W[o,h] (redundant per-block fold, L2-served),
//   e[m] = exp(scale * dot(key_m, wcol))  (max-free softmax: |logit| ~ 1.6),
//   per-block partial sum -> g_psum[bid]. Also preloads its 16 values.
// Barrier: sense-reversing, one atomic per block.
// Phase 2: same block writes output rows n = (bid&63)*16 .. +15 of its batch:
//   out[b,n,m] = v[n] * e[m] / sum_b. psum fold once per block; each thread
//   holds one p-float4 and issues 8 independent STG.128.
// ---------------------------------------------------------------------------
__global__ __launch_bounds__(THREADS_, 1)
void fused_kernel(const float* __restrict__ keys,
                  const float* __restrict__ values,
                  const float* __restrict__ W,
                  float scale,
                  float* __restrict__ out) {
    __shared__ __align__(16) float4 wpart4[16][32];
    __shared__ __align__(16) float4 wcol4[32];
    __shared__ float se[16];
    __shared__ float s_v[16];
    __shared__ float s_rs;

    const int t = threadIdx.x;
    const int warp = t >> 5;        // 0..15
    const int lane = t & 31;
    const int bid = blockIdx.x;     // 0..127
    const int batch = bid >> 6;
    const int rbase = (bid & 63) << 4;   // row base within batch (16 rows)
    const int m = rbase + warp;

    // ---- Phase 1 ----
    // Prefetch the key row first: its DRAM miss overlaps the W fold's.
    const float4 kv = reinterpret_cast<const float4*>(
        keys + ((size_t)batch * M_ + m) * H_)[lane];

    // Preload this block's 16 values (independent of everything else).
    if (warp == 1 && lane < 16)
        s_v[lane] = values[(batch << 10) + rbase + lane];

    // W fold: warp = 8-row o-segment, lane = float4 column.
    {
        const float4* W4 = reinterpret_cast<const float4*>(W);
        float4 acc = make_float4(0.f, 0.f, 0.f, 0.f);
        const int o0 = warp * 8;
        #pragma unroll
        for (int o = 0; o < 8; ++o) {
            const float4 w = W4[(o0 + o) * 32 + lane];
            acc.x += w.x; acc.y += w.y; acc.z += w.z; acc.w += w.w;
        }
        wpart4[warp][lane] = acc;
    }
    __syncthreads();
    if (t < 32) {
        float4 a = make_float4(0.f, 0.f, 0.f, 0.f);
        #pragma unroll
        for (int s = 0; s < 16; ++s) {
            const float4 w = wpart4[s][t];
            a.x += w.x; a.y += w.y; a.z += w.z; a.w += w.w;
        }
        wcol4[t] = a;
    }
    __syncthreads();

    const float4 wc = wcol4[lane];
    float d = kv.x * wc.x + kv.y * wc.y + kv.z * wc.z + kv.w * wc.w;
    #pragma unroll
    for (int off = 16; off; off >>= 1)
        d += __shfl_xor_sync(0xFFFFFFFFu, d, off);

    if (lane == 0) {
        const float e = __expf(scale * d);
        g_e[batch * M_ + m] = e;
        se[warp] = e;
    }
    __syncthreads();
    if (warp == 0) {
        float v = (lane < 16) ? se[lane] : 0.0f;
        #pragma unroll
        for (int off = 16; off; off >>= 1)
            v += __shfl_xor_sync(0xFFFFFFFFu, v, off);
        if (lane == 0) g_psum[bid] = v;
    }
    __syncthreads();   // all phase-1 smem users done before barrier thread spins

    // ---- Grid barrier (sense-reversing; state self-resets each launch) ----
    if (t == 0) {
        const unsigned sense = g_bar_sense;   // read BEFORE arriving (safe:
                                              // flip needs our arrival too)
        __threadfence();                      // publish g_e / g_psum
        if (atomicAdd(&g_bar_count, 1u) == GRID_ - 1u) {
            g_bar_count = 0;                  // reset for next launch
            __threadfence();
            g_bar_sense = sense ^ 1u;         // release
        } else {
            while (g_bar_sense == sense) { }  // L2 spin
        }
    }
    __syncthreads();

    // ---- Phase 2 ----
    // Fold this batch's 64 partials once per block.
    if (t < 32) {
        float s = __ldcg(&g_psum[(batch << 6) + t]) +
                  __ldcg(&g_psum[(batch << 6) + 32 + t]);
        #pragma unroll
        for (int off = 16; off; off >>= 1)
            s += __shfl_xor_sync(0xFFFFFFFFu, s, off);
        if (t == 0) s_rs = 1.0f / s;
    }
    __syncthreads();
    const float rs = s_rs;

    const int col4 = t & 255;       // float4 column 0..255
    const int rh = t >> 8;          // 0..1 (row half)

    const float4 e4 = __ldcg(reinterpret_cast<const float4*>(g_e) +
                             ((batch << 8) | col4));
    const float4 p = make_float4(e4.x * rs, e4.y * rs, e4.z * rs, e4.w * rs);

    float4* out4 = reinterpret_cast<float4*>(out);
    const int n0 = (batch << 10) + rbase + rh * 8;
    #pragma unroll
    for (int j = 0; j < 8; ++j) {
        const float v = s_v[rh * 8 + j];
        float4 o;
        o.x = v * p.x; o.y = v * p.y; o.z = v * p.z; o.w = v * p.w;
        out4[(size_t)(n0 + j) * (M_ / 4) + col4] = o;
    }
}

extern "C" void kernel_launch(void* const* d_in, const int* in_sizes, int n_in,
                              void* d_out, int out_size) {
    // metadata order: queries, keys, values, W, b
    // queries (d_in[0]) and b (d_in[4]) cancel inside the softmax -> unused.
    const float* keys   = (const float*)d_in[1];
    const float* values = (const float*)d_in[2];
    const float* W      = (const float*)d_in[3];

    const float scale = (float)(1.0 / pow((double)H_, 0.4));

    fused_kernel<<<GRID_, THREADS_>>>(keys, values, W, scale, (float*)d_out);
}